// round 7
// baseline (speedup 1.0000x reference)
#include <cuda_runtime.h>
#include <cstdint>

// TitansMemory B=16 L=8192 DK=DV=128 — chunked closed-form (T=16), v2.
// Phases per chunk:
//   A: merged GEMM  C[32 x-rows][48 left-rows] = [W;m;K] . X^T   (no shuffles)
//   B: serial scalar recurrence, 1 broadcast shfl per step (validated in R5)
//   D: rank-16 state update + decay/rescale
// 128 CTAs x 512 thr (1/SM); state W,m in SMEM; k/q/v double-buffered cp.async.

#define T      16
#define L_SEQ  8192
#define NCH    (L_SEQ / T)
#define DK     128
#define PADK   132          // floats per row: LDS.128 conflict-free (4r banks)
#define DAP    52           // C-matrix row pad

using ull = unsigned long long;

__device__ __forceinline__ ull pk(float lo, float hi) {
    ull r; asm("mov.b64 %0,{%1,%2};" : "=l"(r) : "f"(lo), "f"(hi)); return r;
}
__device__ __forceinline__ float hadd2(ull p) {
    float lo, hi; asm("mov.b64 {%0,%1},%2;" : "=f"(lo), "=f"(hi) : "l"(p));
    return lo + hi;
}
__device__ __forceinline__ ull mul2(ull a, ull b) {
    ull d; asm("mul.rn.f32x2 %0,%1,%2;" : "=l"(d) : "l"(a), "l"(b)); return d;
}
__device__ __forceinline__ ull fma2(ull a, ull b, ull c) {
    ull d; asm("fma.rn.f32x2 %0,%1,%2,%3;" : "=l"(d) : "l"(a), "l"(b), "l"(c)); return d;
}
__device__ __forceinline__ unsigned su32(const void* p) {
    return (unsigned)__cvta_generic_to_shared(p);
}
__device__ __forceinline__ void cp16(unsigned s, const void* g) {
    asm volatile("cp.async.cg.shared.global [%0],[%1],16;" :: "r"(s), "l"(g));
}
__device__ __forceinline__ void cp4(unsigned s, const void* g) {
    asm volatile("cp.async.ca.shared.global [%0],[%1],4;" :: "r"(s), "l"(g));
}
__device__ __forceinline__ void cp_commit() {
    asm volatile("cp.async.commit_group;" ::: "memory");
}
__device__ __forceinline__ void cp_wait_all() {
    asm volatile("cp.async.wait_group 0;" ::: "memory");
}

struct Smem {
    float  Wst[32][PADK];        // rows 0-15: What, 16-31: mhat (chunk frame)
    float  xb[2][32][PADK];      // rows 0-15: k_t, 16-31: q_t
    float  vT[2][16][20];        // [row][step]
    float  Da[32][DAP];          // C: [x-row t'][left-row r] (r: 0-31 state, 32-47 k)
    float2 zs[16][20];           // [row][u] -> (zW, zm)
    float  ys[16][20];           // [row][step]
};

__global__ __launch_bounds__(512, 1)
void titans_kernel(const float* __restrict__ Q,
                   const float* __restrict__ K,
                   const float* __restrict__ V,
                   float* __restrict__ Y) {
    static constexpr float cCP[16] = {  // 0.98^i
        1.0f, 0.98f, 0.9604f, 0.941192f, 0.92236816f, 0.9039207968f,
        0.8858423809f, 0.8681255332f, 0.8507630226f, 0.8337477621f,
        0.8170728069f, 0.8007313508f, 0.7847167237f, 0.7690223892f,
        0.7536419414f, 0.7385691035f };
    static constexpr float cCY[16] = {  // 0.98^(i+1)
        0.98f, 0.9604f, 0.941192f, 0.92236816f, 0.9039207968f, 0.8858423809f,
        0.8681255332f, 0.8507630226f, 0.8337477621f, 0.8170728069f,
        0.8007313508f, 0.7847167237f, 0.7690223892f, 0.7536419414f,
        0.7385691035f, 0.7237977214f };
    static constexpr float cS[16] = {   // -0.1*(0.9/0.98)^(i+1)
        -0.09183673469f, -0.08433985839f, -0.07745414463f, -0.07113064017f,
        -0.06532344097f, -0.05999029968f, -0.05509252418f, -0.05059456302f,
        -0.04646378542f, -0.04267021926f, -0.03918632342f, -0.03598663375f,
        -0.03304811221f, -0.03034970510f, -0.02787207213f, -0.02559670445f };
    static constexpr float cA[16] = {   // -0.02/0.98^(i+1)
        -0.02040816327f, -0.02082465640f, -0.02124964939f, -0.02168331570f,
        -0.02212583235f, -0.02257738015f, -0.02303814301f, -0.02350830920f,
        -0.02398807061f, -0.02447762307f, -0.02497716640f, -0.02548690449f,
        -0.02600704540f, -0.02653780143f, -0.02707938921f, -0.02763202981f };
    static constexpr float cB[16] = {   // 0.2/0.9^(i+1)
        0.2222222222f, 0.2469135802f, 0.2743484225f, 0.3048315805f,
        0.3387017561f, 0.3763352846f, 0.4181503162f, 0.4646114624f,
        0.5162349582f, 0.5735943980f, 0.6373271089f, 0.7081412321f,
        0.7868235912f, 0.8742484347f, 0.9713871497f, 1.0793190552f };
    static constexpr float cZW[16] = {  // A(i)+B(i)*(P16-P(i))
        -0.18598573f, -0.18397507f, -0.18127847f, -0.17781047f,
        -0.17347504f, -0.16816631f, -0.16176209f, -0.15414077f,
        -0.14515360f, -0.13463044f, -0.12239474f, -0.10824485f,
        -0.09195752f, -0.07328280f, -0.05194376f, -0.02763203f };
    constexpr float P16F = -0.8369357615f;  // sum cS
    constexpr float C16F = 0.7237977214f;   // 0.98^16
    constexpr float B16F = 0.1853020189f;   // 0.9^16

    extern __shared__ char smem_raw[];
    Smem& S = *reinterpret_cast<Smem*>(smem_raw);

    const int tid  = threadIdx.x;
    const int w    = tid >> 5;
    const int lane = tid & 31;

    const int b     = blockIdx.x >> 3;
    const int vbase = (blockIdx.x & 7) << 4;

    const size_t base = (size_t)b * L_SEQ * DK;
    const float* gk = K + base;
    const float* gq = Q + base;
    const float* gv = V + base;
    float*       gy = Y + base;

    // zero state
    for (int idx = tid; idx < 32 * PADK; idx += 512)
        ((float*)S.Wst)[idx] = 0.0f;

    // preload chunk 0: k rows 0-15, q rows 16-31
    {
        int row = tid >> 5, seg = (tid & 31) * 4;
        cp16(su32(&S.xb[0][row][seg]), gk + row * DK + seg);
        cp16(su32(&S.xb[0][row + 16][seg]), gq + row * DK + seg);
        if (tid < 256) {
            int i = tid >> 4, j = tid & 15;
            cp4(su32(&S.vT[0][j][i]), gv + (size_t)i * DK + vbase + j);
        }
        cp_commit();
        cp_wait_all();
        __syncthreads();
    }

    // phase-A tiling (fixed per thread)
    const int t0  = (w & 3) * 8;
    const int r0  = (w >> 2) * 12;
    const int tt  = t0 + (lane >> 2);
    const int rr  = r0 + (lane & 3);

    for (int chunk = 0; chunk < NCH; ++chunk) {
        const int cur = chunk & 1;
        const int tt0 = chunk * T;
        const float* xbC = &S.xb[cur][0][0];

        // prefetch next chunk
        if (chunk + 1 < NCH) {
            const int nb = cur ^ 1;
            const size_t nt = (size_t)(tt0 + T) * DK;
            int row = tid >> 5, seg = (tid & 31) * 4;
            cp16(su32(&S.xb[nb][row][seg]), gk + nt + row * DK + seg);
            cp16(su32(&S.xb[nb][row + 16][seg]), gq + nt + row * DK + seg);
            if (tid < 256) {
                int i = tid >> 4, j = tid & 15;
                cp4(su32(&S.vT[nb][j][i]), gv + nt + (size_t)i * DK + vbase + j);
            }
        }
        cp_commit();

        // ---- A: C[t'][r] = x_t' . leftrow_r   (t' 0-31, r 0-47) ----
        {
            const float* px = xbC + tt * PADK;
            const float* p1 = (rr      < 32) ? &S.Wst[rr][0]      : xbC + (rr - 32) * PADK;
            const float* p2 = (rr + 4  < 32) ? &S.Wst[rr + 4][0]  : xbC + (rr - 28) * PADK;
            const float* p3 = (rr + 8  < 32) ? &S.Wst[rr + 8][0]  : xbC + (rr - 24) * PADK;
            ull a1 = 0, a2 = 0, a3 = 0;
            #pragma unroll
            for (int dd = 0; dd < DK; dd += 4) {
                ulonglong2 xv = *(const ulonglong2*)(px + dd);
                ulonglong2 s1 = *(const ulonglong2*)(p1 + dd);
                ulonglong2 s2 = *(const ulonglong2*)(p2 + dd);
                ulonglong2 s3 = *(const ulonglong2*)(p3 + dd);
                a1 = fma2(xv.x, s1.x, a1); a1 = fma2(xv.y, s1.y, a1);
                a2 = fma2(xv.x, s2.x, a2); a2 = fma2(xv.y, s2.y, a2);
                a3 = fma2(xv.x, s3.x, a3); a3 = fma2(xv.y, s3.y, a3);
            }
            S.Da[tt][rr]     = hadd2(a1);
            S.Da[tt][rr + 4] = hadd2(a2);
            S.Da[tt][rr + 8] = hadd2(a3);
        }
        __syncthreads();   // C complete

        // ---- B: serial phase (warp = row; lanes 16-31 mirror 0-15) ----
        {
            const int g = lane & 15;
            float Gc[16], Hc[16];
            #pragma unroll
            for (int jj = 0; jj < 4; ++jj) {
                *(float4*)&Gc[jj * 4] = *(const float4*)&S.Da[g][32 + jj * 4];
                *(float4*)&Hc[jj * 4] = *(const float4*)&S.Da[g + 16][32 + jj * 4];
            }
            float wk = S.Da[g][w],      mk = S.Da[g][w + 16];
            float wq = S.Da[g + 16][w], mq = S.Da[g + 16][w + 16];
            const float vv = S.vT[cur][w][g];
            float yg = 0.0f, zwg = 0.0f, zmg = 0.0f;

            #pragma unroll
            for (int i = 0; i < 16; ++i) {
                float r = fmaf(cCP[i], wk, -vv);       // valid in lane i
                r = __shfl_sync(0xffffffffu, r, i, 32);
                const float ta = cA[i] * r, tb = cB[i] * r;
                wk = fmaf(cS[i], mk, wk); wk = fmaf(ta, Gc[i], wk);
                mk = fmaf(tb, Gc[i], mk);
                wq = fmaf(cS[i], mq, wq); wq = fmaf(ta, Hc[i], wq);
                mq = fmaf(tb, Hc[i], mq);
                if (g == i) {
                    yg  = cCY[i] * wq;
                    zwg = cZW[i] * r;
                    zmg = cB[i]  * r;
                }
            }
            if (lane < 16) {
                S.ys[w][g] = yg;
                S.zs[w][g] = make_float2(zwg, zmg);
            }
        }
        __syncthreads();   // z, y complete

        // ---- D: state update + rescale (warp = row pair; lane = d-block) ----
        {
            const int d4 = lane * 4;
            float* Wr = &S.Wst[w][d4];
            float* Mr = &S.Wst[w + 16][d4];
            ulonglong2 Wv = *(ulonglong2*)Wr;
            ulonglong2 Mv = *(ulonglong2*)Mr;
            const ull P16_2 = pk(P16F, P16F);
            Wv.x = fma2(P16_2, Mv.x, Wv.x);
            Wv.y = fma2(P16_2, Mv.y, Wv.y);
            #pragma unroll
            for (int u = 0; u < 16; ++u) {
                const float2 z = S.zs[w][u];
                ulonglong2 kv = *(const ulonglong2*)(xbC + u * PADK + d4);
                const ull zw2 = pk(z.x, z.x), zm2 = pk(z.y, z.y);
                Wv.x = fma2(zw2, kv.x, Wv.x); Wv.y = fma2(zw2, kv.y, Wv.y);
                Mv.x = fma2(zm2, kv.x, Mv.x); Mv.y = fma2(zm2, kv.y, Mv.y);
            }
            const ull c16s = pk(C16F, C16F), b16s = pk(B16F, B16F);
            Wv.x = mul2(c16s, Wv.x); Wv.y = mul2(c16s, Wv.y);
            Mv.x = mul2(b16s, Mv.x); Mv.y = mul2(b16s, Mv.y);
            *(ulonglong2*)Wr = Wv;
            *(ulonglong2*)Mr = Mv;
        }

        // ---- y writeback (reads ys, ordered by bar2 / end-of-chunk bar) ----
        if (tid < 256) {
            int i = tid >> 4, j = tid & 15;
            gy[(size_t)(tt0 + i) * DK + vbase + j] = S.ys[j][i];
        }

        cp_wait_all();
        __syncthreads();   // state + prefetched buffers ready for next chunk
    }
}

extern "C" void kernel_launch(void* const* d_in, const int* in_sizes, int n_in,
                              void* d_out, int out_size) {
    const float* Q = (const float*)d_in[0];
    const float* K = (const float*)d_in[1];
    const float* V = (const float*)d_in[2];
    float* Y = (float*)d_out;
    (void)in_sizes; (void)n_in; (void)out_size;
    cudaFuncSetAttribute(titans_kernel,
                         cudaFuncAttributeMaxDynamicSharedMemorySize,
                         (int)sizeof(Smem));
    titans_kernel<<<128, 512, sizeof(Smem)>>>(Q, K, V, Y);
}

// round 8
// speedup vs baseline: 1.5905x; 1.5905x over previous
#include <cuda_runtime.h>
#include <cstdint>

// TitansMemory B=16 L=8192 DK=DV=128 — direct recurrence v3.
// 2048 (b,v) row-chains; 2 rows per warp (16-lane groups, 8 floats/lane).
// All four dots (Wk, Wq, mq, kq) from PRE-update state -> ONE butterfly
// stage per step (4 interleaved reductions). Rescaled state (R6 math):
//   r = CP_i*(W.k) - v ; W += S_i*m + A_i*r*k ; m += B_i*r*k ;
//   y = CY_i*(W.q + S_i*(m.q) + A_i*r*(k.q)) ; chunk-end rescale.
// 256 CTAs x 128 thr (vgroup=8), 2 CTAs/SM. k/q SMEM swizzled conflict-free.

#define CSTEPS 16
#define L_SEQ  8192
#define NCH    (L_SEQ / CSTEPS)
#define DK     128

using ull = unsigned long long;

__device__ __forceinline__ ull pk(float lo, float hi) {
    ull r; asm("mov.b64 %0,{%1,%2};" : "=l"(r) : "f"(lo), "f"(hi)); return r;
}
__device__ __forceinline__ float hadd2(ull p) {
    float lo, hi; asm("mov.b64 {%0,%1},%2;" : "=f"(lo), "=f"(hi) : "l"(p));
    return lo + hi;
}
__device__ __forceinline__ ull mul2(ull a, ull b) {
    ull d; asm("mul.rn.f32x2 %0,%1,%2;" : "=l"(d) : "l"(a), "l"(b)); return d;
}
__device__ __forceinline__ ull fma2(ull a, ull b, ull c) {
    ull d; asm("fma.rn.f32x2 %0,%1,%2,%3;" : "=l"(d) : "l"(a), "l"(b), "l"(c)); return d;
}
__device__ __forceinline__ ull add2(ull a, ull b) {
    ull d; asm("add.rn.f32x2 %0,%1,%2;" : "=l"(d) : "l"(a), "l"(b)); return d;
}
__device__ __forceinline__ unsigned su32(const void* p) {
    return (unsigned)__cvta_generic_to_shared(p);
}
__device__ __forceinline__ void cp16(unsigned s, const void* g) {
    asm volatile("cp.async.cg.shared.global [%0],[%1],16;" :: "r"(s), "l"(g));
}
__device__ __forceinline__ void cp4(unsigned s, const void* g) {
    asm volatile("cp.async.ca.shared.global [%0],[%1],4;" :: "r"(s), "l"(g));
}
__device__ __forceinline__ void cp_commit() {
    asm volatile("cp.async.commit_group;" ::: "memory");
}
__device__ __forceinline__ void cp_wait_all() {
    asm volatile("cp.async.wait_group 0;" ::: "memory");
}

// even/odd chunk permutation: global float4-chunk c -> smem slot
__device__ __forceinline__ int perm(int c) { return (c >> 1) | ((c & 1) << 4); }

__global__ __launch_bounds__(128, 2)
void titans_kernel(const float* __restrict__ Q,
                   const float* __restrict__ K,
                   const float* __restrict__ V,
                   float* __restrict__ Y) {
    static constexpr float cCP[16] = {  // 0.98^i
        1.0f, 0.98f, 0.9604f, 0.941192f, 0.92236816f, 0.9039207968f,
        0.8858423809f, 0.8681255332f, 0.8507630226f, 0.8337477621f,
        0.8170728069f, 0.8007313508f, 0.7847167237f, 0.7690223892f,
        0.7536419414f, 0.7385691035f };
    static constexpr float cCY[16] = {  // 0.98^(i+1)
        0.98f, 0.9604f, 0.941192f, 0.92236816f, 0.9039207968f, 0.8858423809f,
        0.8681255332f, 0.8507630226f, 0.8337477621f, 0.8170728069f,
        0.8007313508f, 0.7847167237f, 0.7690223892f, 0.7536419414f,
        0.7385691035f, 0.7237977214f };
    static constexpr float cS[16] = {   // -0.1*(0.9/0.98)^(i+1)
        -0.09183673469f, -0.08433985839f, -0.07745414463f, -0.07113064017f,
        -0.06532344097f, -0.05999029968f, -0.05509252418f, -0.05059456302f,
        -0.04646378542f, -0.04267021926f, -0.03918632342f, -0.03598663375f,
        -0.03304811221f, -0.03034970510f, -0.02787207213f, -0.02559670445f };
    static constexpr float cA[16] = {   // -0.02/0.98^(i+1)
        -0.02040816327f, -0.02082465640f, -0.02124964939f, -0.02168331570f,
        -0.02212583235f, -0.02257738015f, -0.02303814301f, -0.02350830920f,
        -0.02398807061f, -0.02447762307f, -0.02497716640f, -0.02548690449f,
        -0.02600704540f, -0.02653780143f, -0.02707938921f, -0.02763202981f };
    static constexpr float cB[16] = {   // 0.2/0.9^(i+1)
        0.2222222222f, 0.2469135802f, 0.2743484225f, 0.3048315805f,
        0.3387017561f, 0.3763352846f, 0.4181503162f, 0.4646114624f,
        0.5162349582f, 0.5735943980f, 0.6373271089f, 0.7081412321f,
        0.7868235912f, 0.8742484347f, 0.9713871497f, 1.0793190552f };
    constexpr float C16F = 0.7237977214f;   // 0.98^16
    constexpr float B16F = 0.1853020189f;   // 0.9^16

    __shared__ float kq[2][2][CSTEPS][DK];  // [buf][k/q][t][swizzled d]
    __shared__ float vT[2][8][20];          // [buf][row][t]
    __shared__ float yb[2][CSTEPS][8];      // [buf][t][row]

    const int tid  = threadIdx.x;
    const int w    = tid >> 5;               // warp 0..3
    const int lane = tid & 31;
    const int g    = lane & 15;              // pos within 16-lane group
    const int half = lane >> 4;              // 0/1
    const int row  = (w << 1) + half;        // 0..7 local row

    const int b     = blockIdx.x >> 4;       // 16 batches
    const int vbase = (blockIdx.x & 15) << 3;// 16 groups x 8 rows

    const size_t base = (size_t)b * L_SEQ * DK;
    const float* gk = K + base;
    const float* gq = Q + base;
    const float* gv = V + base;
    float*       gy = Y + base;

    // state: lane owns What[row, 8g..8g+7], mhat same (4 f32x2 pairs each)
    ull W0 = 0, W1 = 0, W2 = 0, W3 = 0;
    ull M0 = 0, M1 = 0, M2 = 0, M3 = 0;

    // ---- preload chunk 0 (swizzled) ----
    {
        #pragma unroll
        for (int u = 0; u < 4; ++u) {
            int id = u * 128 + tid;          // float4 chunk id: t=id>>5, c=id&31
            int t = id >> 5, c = id & 31;
            cp16(su32(&kq[0][0][t][perm(c) * 4]), gk + t * DK + c * 4);
            cp16(su32(&kq[0][1][t][perm(c) * 4]), gq + t * DK + c * 4);
        }
        {
            int i = tid >> 3, j = tid & 7;
            cp4(su32(&vT[0][j][i]), gv + (size_t)i * DK + vbase + j);
        }
        cp_commit();
        cp_wait_all();
        __syncthreads();
    }

    for (int chunk = 0; chunk < NCH; ++chunk) {
        const int cur = chunk & 1;
        const int t0  = chunk * CSTEPS;

        // prefetch next chunk
        if (chunk + 1 < NCH) {
            const int nb = cur ^ 1;
            const size_t nt = (size_t)(t0 + CSTEPS) * DK;
            #pragma unroll
            for (int u = 0; u < 4; ++u) {
                int id = u * 128 + tid;
                int t = id >> 5, c = id & 31;
                cp16(su32(&kq[nb][0][t][perm(c) * 4]), gk + nt + t * DK + c * 4);
                cp16(su32(&kq[nb][1][t][perm(c) * 4]), gq + nt + t * DK + c * 4);
            }
            {
                int i = tid >> 3, j = tid & 7;
                cp4(su32(&vT[nb][j][i]), gv + nt + (size_t)i * DK + vbase + j);
            }
        }
        cp_commit();

        // stage this thread's v row into registers
        float vreg[CSTEPS];
        #pragma unroll
        for (int jj = 0; jj < 4; ++jj)
            *(float4*)&vreg[jj * 4] = *(const float4*)&vT[cur][row][jj * 4];

        // software pipeline: load step-0 operands
        float4 kA = *(const float4*)&kq[cur][0][0][g * 4];
        float4 kB = *(const float4*)&kq[cur][0][0][64 + g * 4];
        float4 qA = *(const float4*)&kq[cur][1][0][g * 4];
        float4 qB = *(const float4*)&kq[cur][1][0][64 + g * 4];

        // ---- 16 sequential steps ----
        #pragma unroll
        for (int i = 0; i < CSTEPS; ++i) {
            const ull k01 = pk(kA.x, kA.y), k23 = pk(kA.z, kA.w);
            const ull k45 = pk(kB.x, kB.y), k67 = pk(kB.z, kB.w);
            const ull q01 = pk(qA.x, qA.y), q23 = pk(qA.z, qA.w);
            const ull q45 = pk(qB.x, qB.y), q67 = pk(qB.z, qB.w);

            // four dots on pre-update state
            float dwk = hadd2(add2(fma2(W0, k01, mul2(W1, k23)),
                                   fma2(W2, k45, mul2(W3, k67))));
            float dwq = hadd2(add2(fma2(W0, q01, mul2(W1, q23)),
                                   fma2(W2, q45, mul2(W3, q67))));
            float dmq = hadd2(add2(fma2(M0, q01, mul2(M1, q23)),
                                   fma2(M2, q45, mul2(M3, q67))));
            float dkq = hadd2(add2(fma2(k01, q01, mul2(k23, q23)),
                                   fma2(k45, q45, mul2(k67, q67))));

            // prefetch next step's operands while butterfly runs
            if (i + 1 < CSTEPS) {
                kA = *(const float4*)&kq[cur][0][i + 1][g * 4];
                kB = *(const float4*)&kq[cur][0][i + 1][64 + g * 4];
                qA = *(const float4*)&kq[cur][1][i + 1][g * 4];
                qB = *(const float4*)&kq[cur][1][i + 1][64 + g * 4];
            }

            // one butterfly stage: 4 interleaved 16-lane reductions
            #pragma unroll
            for (int off = 8; off; off >>= 1) {
                dwk += __shfl_xor_sync(0xffffffffu, dwk, off);
                dwq += __shfl_xor_sync(0xffffffffu, dwq, off);
                dmq += __shfl_xor_sync(0xffffffffu, dmq, off);
                dkq += __shfl_xor_sync(0xffffffffu, dkq, off);
            }

            const float r  = fmaf(cCP[i], dwk, -vreg[i]);
            const float ta = cA[i] * r;
            const float tb = cB[i] * r;
            const ull a2 = pk(ta, ta);
            const ull b2 = pk(tb, tb);
            const ull s2 = pk(cS[i], cS[i]);

            // W += s*m + a*k ; m += b*k   (prev-step k regs)
            W0 = fma2(s2, M0, W0); W0 = fma2(a2, k01, W0); M0 = fma2(b2, k01, M0);
            W1 = fma2(s2, M1, W1); W1 = fma2(a2, k23, W1); M1 = fma2(b2, k23, M1);
            W2 = fma2(s2, M2, W2); W2 = fma2(a2, k45, W2); M2 = fma2(b2, k45, M2);
            W3 = fma2(s2, M3, W3); W3 = fma2(a2, k67, W3); M3 = fma2(b2, k67, M3);

            // y from pre-update dots (off critical path)
            if (g == i)
                yb[cur][i][row] = cCY[i] *
                    fmaf(ta, dkq, fmaf(cS[i], dmq, dwq));
        }

        // chunk-end rescale
        {
            const ull c16 = pk(C16F, C16F);
            const ull b16 = pk(B16F, B16F);
            W0 = mul2(c16, W0); W1 = mul2(c16, W1);
            W2 = mul2(c16, W2); W3 = mul2(c16, W3);
            M0 = mul2(b16, M0); M1 = mul2(b16, M1);
            M2 = mul2(b16, M2); M3 = mul2(b16, M3);
        }

        cp_wait_all();
        __syncthreads();

        // writeback this chunk's y
        {
            int i = tid >> 3, j = tid & 7;
            gy[(size_t)(t0 + i) * DK + vbase + j] = yb[cur][i][j];
        }
    }
}

extern "C" void kernel_launch(void* const* d_in, const int* in_sizes, int n_in,
                              void* d_out, int out_size) {
    const float* Q = (const float*)d_in[0];
    const float* K = (const float*)d_in[1];
    const float* V = (const float*)d_in[2];
    float* Y = (float*)d_out;
    (void)in_sizes; (void)n_in; (void)out_size;
    titans_kernel<<<256, 128>>>(Q, K, V, Y);
}